// round 14
// baseline (speedup 1.0000x reference)
#include <cuda_runtime.h>
#include <cuda_bf16.h>
#include <cstdint>

// ============================================================
// Swin window attention pipeline, R13:
//   R12 + FMA-polynomial exp2 in attention softmax
//   (theory: attention is MUFU/EX2-throughput-bound)
// ============================================================

#define M_TOTAL 200704          // 64*56*56 = 1568 * 128
typedef unsigned long long u64;

// ---------------- device scratch ----------------
__device__ __nv_bfloat16 g_qkvh[(size_t)M_TOTAL * 768];     // 308 MB
__device__ __nv_bfloat16 g_qkvl[(size_t)M_TOTAL * 768];
__device__ __nv_bfloat16 g_x_hi[(size_t)M_TOTAL * 256];
__device__ __nv_bfloat16 g_x_lo[(size_t)M_TOTAL * 256];
__device__ __nv_bfloat16 g_o_hi[(size_t)M_TOTAL * 256];
__device__ __nv_bfloat16 g_o_lo[(size_t)M_TOTAL * 256];
__device__ __nv_bfloat16 g_wq_hi[768 * 256];
__device__ __nv_bfloat16 g_wq_lo[768 * 256];
__device__ __nv_bfloat16 g_wo_hi[256 * 256];
__device__ __nv_bfloat16 g_wo_lo[256 * 256];
__device__ __align__(16) float g_bias[49 * 52];             // bias table [r][c]

// ---------------- helpers ----------------
__device__ __forceinline__ uint32_t smem_u32(const void* p) {
    uint32_t a;
    asm("{ .reg .u64 t; cvta.to.shared.u64 t, %1; cvt.u32.u64 %0, t; }" : "=r"(a) : "l"(p));
    return a;
}
__device__ __forceinline__ void cpasync16(uint32_t dst, const void* src) {
    asm volatile("cp.async.cg.shared.global [%0], [%1], 16;" :: "r"(dst), "l"(src) : "memory");
}
#define CP_COMMIT() asm volatile("cp.async.commit_group;" ::: "memory")
#define CP_WAIT0()  asm volatile("cp.async.wait_group 0;" ::: "memory")
#define CP_WAIT1()  asm volatile("cp.async.wait_group 1;" ::: "memory")

__device__ __forceinline__ void ldsm_x4(uint32_t* r, uint32_t addr) {
    asm volatile("ldmatrix.sync.aligned.m8n8.x4.shared.b16 {%0,%1,%2,%3}, [%4];"
        : "=r"(r[0]), "=r"(r[1]), "=r"(r[2]), "=r"(r[3]) : "r"(addr));
}

__device__ __forceinline__ void split1(float a, uint16_t& h, uint16_t& l) {
    __nv_bfloat16 hb = __float2bfloat16_rn(a);
    float hf = __bfloat162float(hb);
    __nv_bfloat16 lb = __float2bfloat16_rn(a - hf);
    h = __bfloat16_as_ushort(hb);
    l = __bfloat16_as_ushort(lb);
}

__device__ __forceinline__ void mma16816(float* c, const uint32_t* a, uint32_t b0, uint32_t b1) {
    asm volatile("mma.sync.aligned.m16n8k16.row.col.f32.bf16.bf16.f32 "
        "{%0,%1,%2,%3}, {%4,%5,%6,%7}, {%8,%9}, {%0,%1,%2,%3};"
        : "+f"(c[0]), "+f"(c[1]), "+f"(c[2]), "+f"(c[3])
        : "r"(a[0]), "r"(a[1]), "r"(a[2]), "r"(a[3]), "r"(b0), "r"(b1));
}

// FMA-pipe exp(t) for t <= 0 (t may be -3e38 from masking).
// e^t = 2^(t*log2e); magic-constant round; deg-4 Taylor of e^(f ln2), f in [-0.5,0.5].
__device__ __forceinline__ float fast_exp(float t) {
    float y = fmaxf(t * 1.4426950408889634f, -126.0f);
    float z = y + 12582912.0f;                   // 1.5*2^23: round(y) in mantissa
    int   j = __float_as_int(z) - 0x4B400000;    // j = round(y), j in [-126, 0]
    float f = y - (z - 12582912.0f);             // f in [-0.5, 0.5]
    float p = 0.00961804886f;
    p = fmaf(p, f, 0.0555041087f);
    p = fmaf(p, f, 0.240226507f);
    p = fmaf(p, f, 0.693147181f);
    p = fmaf(p, f, 1.0f);
    return p * __int_as_float((j + 127) << 23);
}

// ---------------- prep kernels ----------------
__global__ void prep_x(const float* __restrict__ x) {
    size_t i = ((size_t)blockIdx.x * 256 + threadIdx.x) * 8;
    float4 a0 = *(const float4*)(x + i);
    float4 a1 = *(const float4*)(x + i + 4);
    uint16_t h[8], l[8];
    split1(a0.x, h[0], l[0]); split1(a0.y, h[1], l[1]);
    split1(a0.z, h[2], l[2]); split1(a0.w, h[3], l[3]);
    split1(a1.x, h[4], l[4]); split1(a1.y, h[5], l[5]);
    split1(a1.z, h[6], l[6]); split1(a1.w, h[7], l[7]);
    uint4 hw, lw;
    hw.x = h[0] | ((uint32_t)h[1] << 16); hw.y = h[2] | ((uint32_t)h[3] << 16);
    hw.z = h[4] | ((uint32_t)h[5] << 16); hw.w = h[6] | ((uint32_t)h[7] << 16);
    lw.x = l[0] | ((uint32_t)l[1] << 16); lw.y = l[2] | ((uint32_t)l[3] << 16);
    lw.z = l[4] | ((uint32_t)l[5] << 16); lw.w = l[6] | ((uint32_t)l[7] << 16);
    *(uint4*)(g_x_hi + i) = hw;
    *(uint4*)(g_x_lo + i) = lw;
}
__global__ void prep_wqkv(const float* __restrict__ w) {
    int k = blockIdx.x;          // 0..255
    int n = threadIdx.x;         // 0..767
    uint16_t h, l;
    split1(w[k * 768 + n], h, l);
    g_wq_hi[n * 256 + k] = __ushort_as_bfloat16(h);
    g_wq_lo[n * 256 + k] = __ushort_as_bfloat16(l);
}
__global__ void prep_wout(const float* __restrict__ w) {
    int k = blockIdx.x;          // 0..255
    int n = threadIdx.x;         // 0..255
    uint16_t h, l;
    split1(w[k * 256 + n], h, l);
    g_wo_hi[n * 256 + k] = __ushort_as_bfloat16(h);
    g_wo_lo[n * 256 + k] = __ushort_as_bfloat16(l);
}
__global__ void prep_bias(const float* __restrict__ pos) {
    int i = blockIdx.x * 128 + threadIdx.x;     // 49*52 = 2548
    if (i < 49 * 52) {
        int r = i / 52, c = i % 52;
        int cc = (c < 49) ? c : 0;
        g_bias[i] = pos[(r / 7 + r % 7) * 13 + (cc / 7 + cc % 7)];
    }
}

// ---------------- pipelined split-bf16 GEMM via mma.sync (R10, frozen) ----------------
#define LDA 40
#define A_ARR (128 * LDA * 2)
#define B_ARR (256 * LDA * 2)
#define OFF_AHI 0
#define OFF_ALO A_ARR
#define OFF_BHI (2 * A_ARR)
#define OFF_BLO (2 * A_ARR + B_ARR)
#define STG_B (2 * A_ARR + 2 * B_ARR)
#define SMO_BIAS (3 * STG_B)
#define SMO_TOTAL (SMO_BIAS + 1024)

__global__ __launch_bounds__(512, 1)
void gemm_mma(const __nv_bfloat16* __restrict__ Ahi,
              const __nv_bfloat16* __restrict__ Alo,
              const __nv_bfloat16* __restrict__ Bhi,
              const __nv_bfloat16* __restrict__ Blo,
              const float* __restrict__ bias,
              float* __restrict__ Cf,
              __nv_bfloat16* __restrict__ Chi,
              __nv_bfloat16* __restrict__ Clo,
              int Ntotal, int nN)
{
    extern __shared__ char smem[];
    float* sBias = (float*)(smem + SMO_BIAS);
    const uint32_t sb = smem_u32(smem);

    const int tid = threadIdx.x;
    const int m0 = (blockIdx.x / nN) * 128;
    const int n0 = (blockIdx.x % nN) * 256;
    const int wid = tid >> 5, lane = tid & 31;
    const int wm = wid & 3, wn = wid >> 2;
    const int g = lane >> 2, tig = lane & 3;

    if (tid < 256) sBias[tid] = bias[n0 + tid];

    const int sra = tid >> 2, sua = tid & 3;
    const size_t goA = (size_t)(m0 + sra) * 256 + sua * 8;
    const uint32_t soA = (uint32_t)(sra * LDA + sua * 8) * 2;
    const int ub0 = tid * 2, ub1 = tid * 2 + 1;
    const int srb0 = ub0 >> 2, sub0 = ub0 & 3;
    const int srb1 = ub1 >> 2, sub1 = ub1 & 3;
    const size_t goB0 = (size_t)(n0 + srb0) * 256 + sub0 * 8;
    const size_t goB1 = (size_t)(n0 + srb1) * 256 + sub1 * 8;
    const uint32_t soB0 = (uint32_t)(srb0 * LDA + sub0 * 8) * 2;
    const uint32_t soB1 = (uint32_t)(srb1 * LDA + sub1 * 8) * 2;

    const int lane15 = lane & 15;
    const int acol8 = (lane >> 4) * 8;
    const uint32_t aoff = (uint32_t)((wm * 32 + lane15) * LDA + acol8) * 2;
    const int brow = (lane & 7) + ((lane & 16) ? 8 : 0);
    const int bcol8 = (lane & 8) ? 8 : 0;
    const uint32_t boff = (uint32_t)((wn * 64 + brow) * LDA + bcol8) * 2;

    float c[2][8][4];
    #pragma unroll
    for (int mf = 0; mf < 2; mf++)
        #pragma unroll
        for (int nf = 0; nf < 8; nf++)
            #pragma unroll
            for (int j = 0; j < 4; j++) c[mf][nf][j] = 0.f;

    #pragma unroll
    for (int pc = 0; pc < 2; pc++) {
        uint32_t st = sb + pc * STG_B;
        size_t ko = (size_t)pc * 32;
        cpasync16(st + OFF_AHI + soA, Ahi + goA + ko);
        cpasync16(st + OFF_ALO + soA, Alo + goA + ko);
        cpasync16(st + OFF_BHI + soB0, Bhi + goB0 + ko);
        cpasync16(st + OFF_BHI + soB1, Bhi + goB1 + ko);
        cpasync16(st + OFF_BLO + soB0, Blo + goB0 + ko);
        cpasync16(st + OFF_BLO + soB1, Blo + goB1 + ko);
        CP_COMMIT();
    }

    #pragma unroll 1
    for (int kc = 0; kc < 8; kc++) {
        CP_WAIT1();
        __syncthreads();

        if (kc + 2 < 8) {
            uint32_t st = sb + ((kc + 2) % 3) * STG_B;
            size_t ko = (size_t)(kc + 2) * 32;
            cpasync16(st + OFF_AHI + soA, Ahi + goA + ko);
            cpasync16(st + OFF_ALO + soA, Alo + goA + ko);
            cpasync16(st + OFF_BHI + soB0, Bhi + goB0 + ko);
            cpasync16(st + OFF_BHI + soB1, Bhi + goB1 + ko);
            cpasync16(st + OFF_BLO + soB0, Blo + goB0 + ko);
            cpasync16(st + OFF_BLO + soB1, Blo + goB1 + ko);
        }
        CP_COMMIT();

        const uint32_t stg = sb + (kc % 3) * STG_B;
        #pragma unroll
        for (int ks = 0; ks < 2; ks++) {
            const uint32_t ksb = stg + ks * 32;
            uint32_t ah[2][4], al[2][4];
            #pragma unroll
            for (int mf = 0; mf < 2; mf++) {
                uint32_t aa = ksb + aoff + mf * (16 * LDA * 2);
                ldsm_x4(ah[mf], aa + OFF_AHI);
                ldsm_x4(al[mf], aa + OFF_ALO);
            }
            #pragma unroll
            for (int nfp = 0; nfp < 4; nfp++) {
                uint32_t ba = ksb + boff + nfp * (16 * LDA * 2);
                uint32_t bh[4], bl[4];
                ldsm_x4(bh, ba + OFF_BHI);
                ldsm_x4(bl, ba + OFF_BLO);
                #pragma unroll
                for (int mf = 0; mf < 2; mf++) {
                    mma16816(c[mf][2 * nfp],     ah[mf], bh[0], bh[1]);
                    mma16816(c[mf][2 * nfp],     ah[mf], bl[0], bl[1]);
                    mma16816(c[mf][2 * nfp],     al[mf], bh[0], bh[1]);
                    mma16816(c[mf][2 * nfp + 1], ah[mf], bh[2], bh[3]);
                    mma16816(c[mf][2 * nfp + 1], ah[mf], bl[2], bl[3]);
                    mma16816(c[mf][2 * nfp + 1], al[mf], bh[2], bh[3]);
                }
            }
        }
    }

    #pragma unroll
    for (int mf = 0; mf < 2; mf++) {
        int row0 = m0 + wm * 32 + mf * 16 + g;
        #pragma unroll
        for (int nf = 0; nf < 8; nf++) {
            int cl = wn * 64 + nf * 8 + tig * 2;
            float bx = sBias[cl], by = sBias[cl + 1];
            float v0x = c[mf][nf][0] + bx, v0y = c[mf][nf][1] + by;
            float v1x = c[mf][nf][2] + bx, v1y = c[mf][nf][3] + by;
            size_t off0 = (size_t)row0 * Ntotal + n0 + cl;
            size_t off1 = (size_t)(row0 + 8) * Ntotal + n0 + cl;
            if (Clo) {
                uint16_t h0, l0, h1, l1;
                split1(v0x, h0, l0); split1(v0y, h1, l1);
                *(uint32_t*)(Chi + off0) = (uint32_t)h0 | ((uint32_t)h1 << 16);
                *(uint32_t*)(Clo + off0) = (uint32_t)l0 | ((uint32_t)l1 << 16);
                split1(v1x, h0, l0); split1(v1y, h1, l1);
                *(uint32_t*)(Chi + off1) = (uint32_t)h0 | ((uint32_t)h1 << 16);
                *(uint32_t*)(Clo + off1) = (uint32_t)l0 | ((uint32_t)l1 << 16);
            } else {
                *(float2*)(Cf + off0) = make_float2(v0x, v0y);
                *(float2*)(Cf + off1) = make_float2(v1x, v1y);
            }
        }
    }
}

// ---------------- tensor-core windowed attention ----------------
__global__ __launch_bounds__(128)
void attn_kernel(const __nv_bfloat16* __restrict__ qkvh,
                 const __nv_bfloat16* __restrict__ qkvl,
                 const float* __restrict__ bias49,
                 __nv_bfloat16* __restrict__ Ohi,
                 __nv_bfloat16* __restrict__ Olo)
{
    __shared__ __align__(16) ushort sQh[64 * 40], sQl[64 * 40];
    __shared__ __align__(16) ushort sKh[64 * 40], sKl[64 * 40];
    __shared__ __align__(16) ushort sVh[32 * 72], sVl[32 * 72];   // V^T [d][c]
    __shared__ __align__(16) float sB[49 * 52];

    const int tid = threadIdx.x;
    const int win = blockIdx.x >> 3, head = blockIdx.x & 7;
    const int b = win >> 6, wh = (win >> 3) & 7, ww = win & 7;
    const int rowbase = (b * 56 + wh * 7) * 56 + ww * 7;
    const int w = tid >> 5, lane = tid & 31;
    const int g = lane >> 2, tig = lane & 3;

    for (int u = tid; u < 784; u += 128) {
        int arr = u & 3, ch = (u >> 2) & 3, t = u >> 4;
        int gr = rowbase + (t / 7) * 56 + t % 7;
        const __nv_bfloat16* src = ((arr & 1) ? qkvl : qkvh)
            + (size_t)gr * 768 + ((arr >> 1) ? 256 : 0) + head * 32 + ch * 8;
        ushort* dst = (arr == 0) ? sQh : (arr == 1) ? sQl : (arr == 2) ? sKh : sKl;
        cpasync16(smem_u32(dst + t * 40 + ch * 8), src);
    }
    for (int u = tid; u < 637; u += 128)
        cpasync16(smem_u32((char*)sB + u * 16), (const char*)bias49 + u * 16);
    CP_COMMIT();

    for (int u = tid; u < 32 * 72 / 2; u += 128) {
        ((uint32_t*)sVh)[u] = 0;
        ((uint32_t*)sVl)[u] = 0;
    }
    __syncthreads();
    for (int u = tid; u < 49 * 16; u += 128) {
        int c = u >> 4, dp = u & 15;
        int gr = rowbase + (c / 7) * 56 + c % 7;
        size_t off = (size_t)gr * 768 + 512 + head * 32 + dp * 2;
        uint32_t vh = *(const uint32_t*)(qkvh + off);
        uint32_t vl = *(const uint32_t*)(qkvl + off);
        sVh[(2 * dp) * 72 + c] = (ushort)vh;
        sVh[(2 * dp + 1) * 72 + c] = (ushort)(vh >> 16);
        sVl[(2 * dp) * 72 + c] = (ushort)vl;
        sVl[(2 * dp + 1) * 72 + c] = (ushort)(vl >> 16);
    }
    CP_WAIT0();
    __syncthreads();

    const int lane15 = lane & 15;
    const int acol8 = (lane >> 4) * 8;
    const uint32_t aoff = (uint32_t)((w * 16 + lane15) * 40 + acol8) * 2;
    const int brow = (lane & 7) + ((lane & 16) ? 8 : 0);
    const int bcol8 = (lane & 8) ? 8 : 0;
    const uint32_t boffK = (uint32_t)(brow * 40 + bcol8) * 2;
    const uint32_t boffV = (uint32_t)(brow * 72 + bcol8) * 2;
    const uint32_t qh_b = smem_u32(sQh), ql_b = smem_u32(sQl);
    const uint32_t kh_b = smem_u32(sKh), kl_b = smem_u32(sKl);
    const uint32_t vh_b = smem_u32(sVh), vl_b = smem_u32(sVl);

    // ---- S = Q @ K^T ----
    float s[8][4];
    #pragma unroll
    for (int nf = 0; nf < 8; nf++)
        #pragma unroll
        for (int j = 0; j < 4; j++) s[nf][j] = 0.f;

    #pragma unroll
    for (int ks = 0; ks < 2; ks++) {
        uint32_t ah[4], al[4];
        ldsm_x4(ah, qh_b + aoff + ks * 32);
        ldsm_x4(al, ql_b + aoff + ks * 32);
        #pragma unroll
        for (int nfp = 0; nfp < 4; nfp++) {
            uint32_t bh[4], bl[4];
            uint32_t ba = boffK + nfp * (16 * 40 * 2) + ks * 32;
            ldsm_x4(bh, kh_b + ba);
            ldsm_x4(bl, kl_b + ba);
            mma16816(s[2 * nfp],     ah, bh[0], bh[1]);
            mma16816(s[2 * nfp],     ah, bl[0], bl[1]);
            mma16816(s[2 * nfp],     al, bh[0], bh[1]);
            mma16816(s[2 * nfp + 1], ah, bh[2], bh[3]);
            mma16816(s[2 * nfp + 1], ah, bl[2], bl[3]);
            mma16816(s[2 * nfp + 1], al, bh[2], bh[3]);
        }
    }

    // ---- scale + bias + mask ----
    const int r0 = w * 16 + g, r1 = r0 + 8;
    const int rA = (r0 > 48) ? 48 : r0;
    const int rB = (r1 > 48) ? 48 : r1;
    const float scl = 5.656854249492381f;
    float m0 = -3.0e38f, m1 = -3.0e38f;
    #pragma unroll
    for (int nf = 0; nf < 8; nf++) {
        int c0 = nf * 8 + tig * 2;
        float bAx = 0.f, bAy = 0.f, bBx = 0.f, bBy = 0.f;
        if (c0 <= 48) {
            float2 t0 = *(const float2*)&sB[rA * 52 + c0]; bAx = t0.x; bAy = t0.y;
            float2 t1 = *(const float2*)&sB[rB * 52 + c0]; bBx = t1.x; bBy = t1.y;
        }
        s[nf][0] = (c0     < 49) ? s[nf][0] * scl + bAx : -3.0e38f;
        s[nf][1] = (c0 + 1 < 49) ? s[nf][1] * scl + bAy : -3.0e38f;
        s[nf][2] = (c0     < 49) ? s[nf][2] * scl + bBx : -3.0e38f;
        s[nf][3] = (c0 + 1 < 49) ? s[nf][3] * scl + bBy : -3.0e38f;
        m0 = fmaxf(m0, fmaxf(s[nf][0], s[nf][1]));
        m1 = fmaxf(m1, fmaxf(s[nf][2], s[nf][3]));
    }
    m0 = fmaxf(m0, __shfl_xor_sync(0xffffffffu, m0, 1));
    m0 = fmaxf(m0, __shfl_xor_sync(0xffffffffu, m0, 2));
    m1 = fmaxf(m1, __shfl_xor_sync(0xffffffffu, m1, 1));
    m1 = fmaxf(m1, __shfl_xor_sync(0xffffffffu, m1, 2));

    float sum0 = 0.f, sum1 = 0.f;
    #pragma unroll
    for (int nf = 0; nf < 8; nf++) {
        s[nf][0] = fast_exp(s[nf][0] - m0);
        s[nf][1] = fast_exp(s[nf][1] - m0);
        s[nf][2] = fast_exp(s[nf][2] - m1);
        s[nf][3] = fast_exp(s[nf][3] - m1);
        sum0 += s[nf][0] + s[nf][1];
        sum1 += s[nf][2] + s[nf][3];
    }
    sum0 += __shfl_xor_sync(0xffffffffu, sum0, 1);
    sum0 += __shfl_xor_sync(0xffffffffu, sum0, 2);
    sum1 += __shfl_xor_sync(0xffffffffu, sum1, 1);
    sum1 += __shfl_xor_sync(0xffffffffu, sum1, 2);
    float inv0 = 1.f / sum0, inv1 = 1.f / sum1;

    // ---- pack P as bf16 hi/lo A-fragments ----
    uint32_t php[8][2], plp[8][2];
    #pragma unroll
    for (int nf = 0; nf < 8; nf++) {
        uint16_t h0, l0, h1, l1, h2, l2, h3, l3;
        split1(s[nf][0] * inv0, h0, l0);
        split1(s[nf][1] * inv0, h1, l1);
        split1(s[nf][2] * inv1, h2, l2);
        split1(s[nf][3] * inv1, h3, l3);
        php[nf][0] = (uint32_t)h0 | ((uint32_t)h1 << 16);
        plp[nf][0] = (uint32_t)l0 | ((uint32_t)l1 << 16);
        php[nf][1] = (uint32_t)h2 | ((uint32_t)h3 << 16);
        plp[nf][1] = (uint32_t)l2 | ((uint32_t)l3 << 16);
    }

    // ---- O = P @ V ----
    float o[4][4];
    #pragma unroll
    for (int nf = 0; nf < 4; nf++)
        #pragma unroll
        for (int j = 0; j < 4; j++) o[nf][j] = 0.f;

    #pragma unroll
    for (int ks = 0; ks < 4; ks++) {
        uint32_t ah[4] = {php[2 * ks][0], php[2 * ks][1], php[2 * ks + 1][0], php[2 * ks + 1][1]};
        uint32_t al[4] = {plp[2 * ks][0], plp[2 * ks][1], plp[2 * ks + 1][0], plp[2 * ks + 1][1]};
        #pragma unroll
        for (int nfp = 0; nfp < 2; nfp++) {
            uint32_t bh[4], bl[4];
            uint32_t ba = boffV + nfp * (16 * 72 * 2) + ks * 32;
            ldsm_x4(bh, vh_b + ba);
            ldsm_x4(bl, vl_b + ba);
            mma16816(o[2 * nfp],     ah, bh[0], bh[1]);
            mma16816(o[2 * nfp],     ah, bl[0], bl[1]);
            mma16816(o[2 * nfp],     al, bh[0], bh[1]);
            mma16816(o[2 * nfp + 1], ah, bh[2], bh[3]);
            mma16816(o[2 * nfp + 1], ah, bl[2], bl[3]);
            mma16816(o[2 * nfp + 1], al, bh[2], bh[3]);
        }
    }

    // ---- store O hi/lo ----
    if (r0 <= 48) {
        int gr = rowbase + (r0 / 7) * 56 + r0 % 7;
        size_t base = (size_t)gr * 256 + head * 32;
        #pragma unroll
        for (int nf = 0; nf < 4; nf++) {
            int d = nf * 8 + tig * 2;
            uint16_t h0, l0, h1, l1;
            split1(o[nf][0], h0, l0);
            split1(o[nf][1], h1, l1);
            *(uint32_t*)(Ohi + base + d) = (uint32_t)h0 | ((uint32_t)h1 << 16);
            *(uint32_t*)(Olo + base + d) = (uint32_t)l0 | ((uint32_t)l1 << 16);
        }
    }
    if (r1 <= 48) {
        int gr = rowbase + (r1 / 7) * 56 + r1 % 7;
        size_t base = (size_t)gr * 256 + head * 32;
        #pragma unroll
        for (int nf = 0; nf < 4; nf++) {
            int d = nf * 8 + tig * 2;
            uint16_t h0, l0, h1, l1;
            split1(o[nf][2], h0, l0);
            split1(o[nf][3], h1, l1);
            *(uint32_t*)(Ohi + base + d) = (uint32_t)h0 | ((uint32_t)h1 << 16);
            *(uint32_t*)(Olo + base + d) = (uint32_t)l0 | ((uint32_t)l1 << 16);
        }
    }
}

// ---------------- host launcher ----------------
extern "C" void kernel_launch(void* const* d_in, const int* in_sizes, int n_in,
                              void* d_out, int out_size)
{
    const float* x    = (const float*)d_in[0];
    const float* pos  = (const float*)d_in[1];
    const float* wqkv = (const float*)d_in[2];
    const float* bqkv = (const float*)d_in[3];
    const float* wout = (const float*)d_in[4];
    const float* bout = (const float*)d_in[5];
    float* out = (float*)d_out;

    void *p_qkvh, *p_qkvl, *p_xh, *p_xl, *p_oh, *p_ol, *p_wqh, *p_wql, *p_woh, *p_wol, *p_bias;
    cudaGetSymbolAddress(&p_qkvh, g_qkvh);
    cudaGetSymbolAddress(&p_qkvl, g_qkvl);
    cudaGetSymbolAddress(&p_xh, g_x_hi);
    cudaGetSymbolAddress(&p_xl, g_x_lo);
    cudaGetSymbolAddress(&p_oh, g_o_hi);
    cudaGetSymbolAddress(&p_ol, g_o_lo);
    cudaGetSymbolAddress(&p_wqh, g_wq_hi);
    cudaGetSymbolAddress(&p_wql, g_wq_lo);
    cudaGetSymbolAddress(&p_woh, g_wo_hi);
    cudaGetSymbolAddress(&p_wol, g_wo_lo);
    cudaGetSymbolAddress(&p_bias, g_bias);

    cudaFuncSetAttribute(gemm_mma, cudaFuncAttributeMaxDynamicSharedMemorySize, SMO_TOTAL);

    prep_x<<<M_TOTAL * 256 / (256 * 8), 256>>>(x);
    prep_wqkv<<<256, 768>>>(wqkv);
    prep_wout<<<256, 256>>>(wout);
    prep_bias<<<20, 128>>>(pos);

    // GEMM1: qkv = x @ w_qkv + b_qkv -> bf16 hi/lo
    gemm_mma<<<(M_TOTAL / 128) * 3, 512, SMO_TOTAL>>>(
        (const __nv_bfloat16*)p_xh, (const __nv_bfloat16*)p_xl,
        (const __nv_bfloat16*)p_wqh, (const __nv_bfloat16*)p_wql,
        bqkv, nullptr, (__nv_bfloat16*)p_qkvh, (__nv_bfloat16*)p_qkvl, 768, 3);

    // tensor-core windowed attention: 4096 windows x 8 heads
    attn_kernel<<<32768, 128>>>(
        (const __nv_bfloat16*)p_qkvh, (const __nv_bfloat16*)p_qkvl,
        (const float*)p_bias,
        (__nv_bfloat16*)p_oh, (__nv_bfloat16*)p_ol);

    // GEMM2: out = O @ w_out + b_out -> fp32
    gemm_mma<<<(M_TOTAL / 128) * 1, 512, SMO_TOTAL>>>(
        (const __nv_bfloat16*)p_oh, (const __nv_bfloat16*)p_ol,
        (const __nv_bfloat16*)p_woh, (const __nv_bfloat16*)p_wol,
        bout, out, nullptr, nullptr, 256, 1);
}

// round 15
// speedup vs baseline: 1.0132x; 1.0132x over previous
#include <cuda_runtime.h>
#include <cuda_bf16.h>
#include <cstdint>

// ============================================================
// Swin window attention pipeline, R15:
//   R12 base (best) + attention V path via ldmatrix.trans:
//   all of Q/K/V staged by cp.async, single barrier, no scalar
//   V-transpose. GEMMs frozen (R10 config).
// ============================================================

#define M_TOTAL 200704          // 64*56*56 = 1568 * 128
typedef unsigned long long u64;

// ---------------- device scratch ----------------
__device__ __nv_bfloat16 g_qkvh[(size_t)M_TOTAL * 768];     // 308 MB
__device__ __nv_bfloat16 g_qkvl[(size_t)M_TOTAL * 768];
__device__ __nv_bfloat16 g_x_hi[(size_t)M_TOTAL * 256];
__device__ __nv_bfloat16 g_x_lo[(size_t)M_TOTAL * 256];
__device__ __nv_bfloat16 g_o_hi[(size_t)M_TOTAL * 256];
__device__ __nv_bfloat16 g_o_lo[(size_t)M_TOTAL * 256];
__device__ __nv_bfloat16 g_wq_hi[768 * 256];
__device__ __nv_bfloat16 g_wq_lo[768 * 256];
__device__ __nv_bfloat16 g_wo_hi[256 * 256];
__device__ __nv_bfloat16 g_wo_lo[256 * 256];
__device__ __align__(16) float g_bias[49 * 52];             // bias table [r][c]

// ---------------- helpers ----------------
__device__ __forceinline__ uint32_t smem_u32(const void* p) {
    uint32_t a;
    asm("{ .reg .u64 t; cvta.to.shared.u64 t, %1; cvt.u32.u64 %0, t; }" : "=r"(a) : "l"(p));
    return a;
}
__device__ __forceinline__ void cpasync16(uint32_t dst, const void* src) {
    asm volatile("cp.async.cg.shared.global [%0], [%1], 16;" :: "r"(dst), "l"(src) : "memory");
}
#define CP_COMMIT() asm volatile("cp.async.commit_group;" ::: "memory")
#define CP_WAIT0()  asm volatile("cp.async.wait_group 0;" ::: "memory")
#define CP_WAIT1()  asm volatile("cp.async.wait_group 1;" ::: "memory")

__device__ __forceinline__ void ldsm_x4(uint32_t* r, uint32_t addr) {
    asm volatile("ldmatrix.sync.aligned.m8n8.x4.shared.b16 {%0,%1,%2,%3}, [%4];"
        : "=r"(r[0]), "=r"(r[1]), "=r"(r[2]), "=r"(r[3]) : "r"(addr));
}
__device__ __forceinline__ void ldsm_x4_trans(uint32_t* r, uint32_t addr) {
    asm volatile("ldmatrix.sync.aligned.m8n8.x4.trans.shared.b16 {%0,%1,%2,%3}, [%4];"
        : "=r"(r[0]), "=r"(r[1]), "=r"(r[2]), "=r"(r[3]) : "r"(addr));
}

__device__ __forceinline__ void split1(float a, uint16_t& h, uint16_t& l) {
    __nv_bfloat16 hb = __float2bfloat16_rn(a);
    float hf = __bfloat162float(hb);
    __nv_bfloat16 lb = __float2bfloat16_rn(a - hf);
    h = __bfloat16_as_ushort(hb);
    l = __bfloat16_as_ushort(lb);
}

__device__ __forceinline__ void mma16816(float* c, const uint32_t* a, uint32_t b0, uint32_t b1) {
    asm volatile("mma.sync.aligned.m16n8k16.row.col.f32.bf16.bf16.f32 "
        "{%0,%1,%2,%3}, {%4,%5,%6,%7}, {%8,%9}, {%0,%1,%2,%3};"
        : "+f"(c[0]), "+f"(c[1]), "+f"(c[2]), "+f"(c[3])
        : "r"(a[0]), "r"(a[1]), "r"(a[2]), "r"(a[3]), "r"(b0), "r"(b1));
}

// ---------------- prep kernels ----------------
__global__ void prep_x(const float* __restrict__ x) {
    size_t i = ((size_t)blockIdx.x * 256 + threadIdx.x) * 8;
    float4 a0 = *(const float4*)(x + i);
    float4 a1 = *(const float4*)(x + i + 4);
    uint16_t h[8], l[8];
    split1(a0.x, h[0], l[0]); split1(a0.y, h[1], l[1]);
    split1(a0.z, h[2], l[2]); split1(a0.w, h[3], l[3]);
    split1(a1.x, h[4], l[4]); split1(a1.y, h[5], l[5]);
    split1(a1.z, h[6], l[6]); split1(a1.w, h[7], l[7]);
    uint4 hw, lw;
    hw.x = h[0] | ((uint32_t)h[1] << 16); hw.y = h[2] | ((uint32_t)h[3] << 16);
    hw.z = h[4] | ((uint32_t)h[5] << 16); hw.w = h[6] | ((uint32_t)h[7] << 16);
    lw.x = l[0] | ((uint32_t)l[1] << 16); lw.y = l[2] | ((uint32_t)l[3] << 16);
    lw.z = l[4] | ((uint32_t)l[5] << 16); lw.w = l[6] | ((uint32_t)l[7] << 16);
    *(uint4*)(g_x_hi + i) = hw;
    *(uint4*)(g_x_lo + i) = lw;
}
__global__ void prep_wqkv(const float* __restrict__ w) {
    int k = blockIdx.x;          // 0..255
    int n = threadIdx.x;         // 0..767
    uint16_t h, l;
    split1(w[k * 768 + n], h, l);
    g_wq_hi[n * 256 + k] = __ushort_as_bfloat16(h);
    g_wq_lo[n * 256 + k] = __ushort_as_bfloat16(l);
}
__global__ void prep_wout(const float* __restrict__ w) {
    int k = blockIdx.x;          // 0..255
    int n = threadIdx.x;         // 0..255
    uint16_t h, l;
    split1(w[k * 256 + n], h, l);
    g_wo_hi[n * 256 + k] = __ushort_as_bfloat16(h);
    g_wo_lo[n * 256 + k] = __ushort_as_bfloat16(l);
}
__global__ void prep_bias(const float* __restrict__ pos) {
    int i = blockIdx.x * 128 + threadIdx.x;     // 49*52 = 2548
    if (i < 49 * 52) {
        int r = i / 52, c = i % 52;
        int cc = (c < 49) ? c : 0;
        g_bias[i] = pos[(r / 7 + r % 7) * 13 + (cc / 7 + cc % 7)];
    }
}

// ---------------- pipelined split-bf16 GEMM via mma.sync (R10, frozen) ----------------
#define LDA 40
#define A_ARR (128 * LDA * 2)
#define B_ARR (256 * LDA * 2)
#define OFF_AHI 0
#define OFF_ALO A_ARR
#define OFF_BHI (2 * A_ARR)
#define OFF_BLO (2 * A_ARR + B_ARR)
#define STG_B (2 * A_ARR + 2 * B_ARR)
#define SMO_BIAS (3 * STG_B)
#define SMO_TOTAL (SMO_BIAS + 1024)

__global__ __launch_bounds__(512, 1)
void gemm_mma(const __nv_bfloat16* __restrict__ Ahi,
              const __nv_bfloat16* __restrict__ Alo,
              const __nv_bfloat16* __restrict__ Bhi,
              const __nv_bfloat16* __restrict__ Blo,
              const float* __restrict__ bias,
              float* __restrict__ Cf,
              __nv_bfloat16* __restrict__ Chi,
              __nv_bfloat16* __restrict__ Clo,
              int Ntotal, int nN)
{
    extern __shared__ char smem[];
    float* sBias = (float*)(smem + SMO_BIAS);
    const uint32_t sb = smem_u32(smem);

    const int tid = threadIdx.x;
    const int m0 = (blockIdx.x / nN) * 128;
    const int n0 = (blockIdx.x % nN) * 256;
    const int wid = tid >> 5, lane = tid & 31;
    const int wm = wid & 3, wn = wid >> 2;
    const int g = lane >> 2, tig = lane & 3;

    if (tid < 256) sBias[tid] = bias[n0 + tid];

    const int sra = tid >> 2, sua = tid & 3;
    const size_t goA = (size_t)(m0 + sra) * 256 + sua * 8;
    const uint32_t soA = (uint32_t)(sra * LDA + sua * 8) * 2;
    const int ub0 = tid * 2, ub1 = tid * 2 + 1;
    const int srb0 = ub0 >> 2, sub0 = ub0 & 3;
    const int srb1 = ub1 >> 2, sub1 = ub1 & 3;
    const size_t goB0 = (size_t)(n0 + srb0) * 256 + sub0 * 8;
    const size_t goB1 = (size_t)(n0 + srb1) * 256 + sub1 * 8;
    const uint32_t soB0 = (uint32_t)(srb0 * LDA + sub0 * 8) * 2;
    const uint32_t soB1 = (uint32_t)(srb1 * LDA + sub1 * 8) * 2;

    const int lane15 = lane & 15;
    const int acol8 = (lane >> 4) * 8;
    const uint32_t aoff = (uint32_t)((wm * 32 + lane15) * LDA + acol8) * 2;
    const int brow = (lane & 7) + ((lane & 16) ? 8 : 0);
    const int bcol8 = (lane & 8) ? 8 : 0;
    const uint32_t boff = (uint32_t)((wn * 64 + brow) * LDA + bcol8) * 2;

    float c[2][8][4];
    #pragma unroll
    for (int mf = 0; mf < 2; mf++)
        #pragma unroll
        for (int nf = 0; nf < 8; nf++)
            #pragma unroll
            for (int j = 0; j < 4; j++) c[mf][nf][j] = 0.f;

    #pragma unroll
    for (int pc = 0; pc < 2; pc++) {
        uint32_t st = sb + pc * STG_B;
        size_t ko = (size_t)pc * 32;
        cpasync16(st + OFF_AHI + soA, Ahi + goA + ko);
        cpasync16(st + OFF_ALO + soA, Alo + goA + ko);
        cpasync16(st + OFF_BHI + soB0, Bhi + goB0 + ko);
        cpasync16(st + OFF_BHI + soB1, Bhi + goB1 + ko);
        cpasync16(st + OFF_BLO + soB0, Blo + goB0 + ko);
        cpasync16(st + OFF_BLO + soB1, Blo + goB1 + ko);
        CP_COMMIT();
    }

    #pragma unroll 1
    for (int kc = 0; kc < 8; kc++) {
        CP_WAIT1();
        __syncthreads();

        if (kc + 2 < 8) {
            uint32_t st = sb + ((kc + 2) % 3) * STG_B;
            size_t ko = (size_t)(kc + 2) * 32;
            cpasync16(st + OFF_AHI + soA, Ahi + goA + ko);
            cpasync16(st + OFF_ALO + soA, Alo + goA + ko);
            cpasync16(st + OFF_BHI + soB0, Bhi + goB0 + ko);
            cpasync16(st + OFF_BHI + soB1, Bhi + goB1 + ko);
            cpasync16(st + OFF_BLO + soB0, Blo + goB0 + ko);
            cpasync16(st + OFF_BLO + soB1, Blo + goB1 + ko);
        }
        CP_COMMIT();

        const uint32_t stg = sb + (kc % 3) * STG_B;
        #pragma unroll
        for (int ks = 0; ks < 2; ks++) {
            const uint32_t ksb = stg + ks * 32;
            uint32_t ah[2][4], al[2][4];
            #pragma unroll
            for (int mf = 0; mf < 2; mf++) {
                uint32_t aa = ksb + aoff + mf * (16 * LDA * 2);
                ldsm_x4(ah[mf], aa + OFF_AHI);
                ldsm_x4(al[mf], aa + OFF_ALO);
            }
            #pragma unroll
            for (int nfp = 0; nfp < 4; nfp++) {
                uint32_t ba = ksb + boff + nfp * (16 * LDA * 2);
                uint32_t bh[4], bl[4];
                ldsm_x4(bh, ba + OFF_BHI);
                ldsm_x4(bl, ba + OFF_BLO);
                #pragma unroll
                for (int mf = 0; mf < 2; mf++) {
                    mma16816(c[mf][2 * nfp],     ah[mf], bh[0], bh[1]);
                    mma16816(c[mf][2 * nfp],     ah[mf], bl[0], bl[1]);
                    mma16816(c[mf][2 * nfp],     al[mf], bh[0], bh[1]);
                    mma16816(c[mf][2 * nfp + 1], ah[mf], bh[2], bh[3]);
                    mma16816(c[mf][2 * nfp + 1], ah[mf], bl[2], bl[3]);
                    mma16816(c[mf][2 * nfp + 1], al[mf], bh[2], bh[3]);
                }
            }
        }
    }

    #pragma unroll
    for (int mf = 0; mf < 2; mf++) {
        int row0 = m0 + wm * 32 + mf * 16 + g;
        #pragma unroll
        for (int nf = 0; nf < 8; nf++) {
            int cl = wn * 64 + nf * 8 + tig * 2;
            float bx = sBias[cl], by = sBias[cl + 1];
            float v0x = c[mf][nf][0] + bx, v0y = c[mf][nf][1] + by;
            float v1x = c[mf][nf][2] + bx, v1y = c[mf][nf][3] + by;
            size_t off0 = (size_t)row0 * Ntotal + n0 + cl;
            size_t off1 = (size_t)(row0 + 8) * Ntotal + n0 + cl;
            if (Clo) {
                uint16_t h0, l0, h1, l1;
                split1(v0x, h0, l0); split1(v0y, h1, l1);
                *(uint32_t*)(Chi + off0) = (uint32_t)h0 | ((uint32_t)h1 << 16);
                *(uint32_t*)(Clo + off0) = (uint32_t)l0 | ((uint32_t)l1 << 16);
                split1(v1x, h0, l0); split1(v1y, h1, l1);
                *(uint32_t*)(Chi + off1) = (uint32_t)h0 | ((uint32_t)h1 << 16);
                *(uint32_t*)(Clo + off1) = (uint32_t)l0 | ((uint32_t)l1 << 16);
            } else {
                *(float2*)(Cf + off0) = make_float2(v0x, v0y);
                *(float2*)(Cf + off1) = make_float2(v1x, v1y);
            }
        }
    }
}

// ---------------- tensor-core windowed attention ----------------
// Block = (window, head): 32768 blocks x 128 threads.
// Q/K/V all staged row-major [64][40] via cp.async; V consumed via
// ldmatrix.trans as the P@V B operand. ONE barrier total.

__global__ __launch_bounds__(128)
void attn_kernel(const __nv_bfloat16* __restrict__ qkvh,
                 const __nv_bfloat16* __restrict__ qkvl,
                 const float* __restrict__ bias49,
                 __nv_bfloat16* __restrict__ Ohi,
                 __nv_bfloat16* __restrict__ Olo)
{
    __shared__ __align__(16) ushort sQh[64 * 40], sQl[64 * 40];
    __shared__ __align__(16) ushort sKh[64 * 40], sKl[64 * 40];
    __shared__ __align__(16) ushort sVh[64 * 40], sVl[64 * 40];   // V row-major [c][d]
    __shared__ __align__(16) float sB[49 * 52];

    const int tid = threadIdx.x;
    const int win = blockIdx.x >> 3, head = blockIdx.x & 7;
    const int b = win >> 6, wh = (win >> 3) & 7, ww = win & 7;
    const int rowbase = (b * 56 + wh * 7) * 56 + ww * 7;
    const int w = tid >> 5, lane = tid & 31;
    const int g = lane >> 2, tig = lane & 3;

    // ---- cp.async Q,K,V hi/lo: 49 rows x 4 chunks x 6 arrays ----
    for (int u = tid; u < 1176; u += 128) {
        int t = u / 24, rem = u % 24;
        int arr = rem >> 2, ch = rem & 3;            // arr: 0 Qh,1 Ql,2 Kh,3 Kl,4 Vh,5 Vl
        int gr = rowbase + (t / 7) * 56 + t % 7;
        const __nv_bfloat16* src = ((arr & 1) ? qkvl : qkvh)
            + (size_t)gr * 768 + (arr >> 1) * 256 + head * 32 + ch * 8;
        ushort* dst = (arr == 0) ? sQh : (arr == 1) ? sQl : (arr == 2) ? sKh
                    : (arr == 3) ? sKl : (arr == 4) ? sVh : sVl;
        cpasync16(smem_u32(dst + t * 40 + ch * 8), src);
    }
    for (int u = tid; u < 637; u += 128)             // bias 49*52*4 = 10192 B
        cpasync16(smem_u32((char*)sB + u * 16), (const char*)bias49 + u * 16);
    CP_COMMIT();

    // ---- zero V pad rows 49..63 (P pad cols are ~1e-38, V pad must be 0) ----
    {
        uint32_t* vz0 = (uint32_t*)(sVh + 49 * 40);  // 15*40 ushort = 300 u32
        uint32_t* vz1 = (uint32_t*)(sVl + 49 * 40);
        for (int u = tid; u < 300; u += 128) { vz0[u] = 0; vz1[u] = 0; }
    }
    CP_WAIT0();
    __syncthreads();

    // ---- fragment addresses ----
    const int lane15 = lane & 15;
    const int acol8 = (lane >> 4) * 8;
    const uint32_t aoff = (uint32_t)((w * 16 + lane15) * 40 + acol8) * 2;
    const int brow = (lane & 7) + ((lane & 16) ? 8 : 0);
    const int bcol8 = (lane & 8) ? 8 : 0;
    const uint32_t boffK = (uint32_t)(brow * 40 + bcol8) * 2;
    // V (trans): rows = token k, cols = d; lane&15 -> row, lane>>4 -> col half
    const uint32_t boffV = (uint32_t)(lane15 * 40 + (lane >> 4) * 8) * 2;
    const uint32_t qh_b = smem_u32(sQh), ql_b = smem_u32(sQl);
    const uint32_t kh_b = smem_u32(sKh), kl_b = smem_u32(sKl);
    const uint32_t vh_b = smem_u32(sVh), vl_b = smem_u32(sVl);

    // ---- S = Q @ K^T ----
    float s[8][4];
    #pragma unroll
    for (int nf = 0; nf < 8; nf++)
        #pragma unroll
        for (int j = 0; j < 4; j++) s[nf][j] = 0.f;

    #pragma unroll
    for (int ks = 0; ks < 2; ks++) {
        uint32_t ah[4], al[4];
        ldsm_x4(ah, qh_b + aoff + ks * 32);
        ldsm_x4(al, ql_b + aoff + ks * 32);
        #pragma unroll
        for (int nfp = 0; nfp < 4; nfp++) {
            uint32_t bh[4], bl[4];
            uint32_t ba = boffK + nfp * (16 * 40 * 2) + ks * 32;
            ldsm_x4(bh, kh_b + ba);
            ldsm_x4(bl, kl_b + ba);
            mma16816(s[2 * nfp],     ah, bh[0], bh[1]);
            mma16816(s[2 * nfp],     ah, bl[0], bl[1]);
            mma16816(s[2 * nfp],     al, bh[0], bh[1]);
            mma16816(s[2 * nfp + 1], ah, bh[2], bh[3]);
            mma16816(s[2 * nfp + 1], ah, bl[2], bl[3]);
            mma16816(s[2 * nfp + 1], al, bh[2], bh[3]);
        }
    }

    // ---- scale + bias + mask ----
    const int r0 = w * 16 + g, r1 = r0 + 8;
    const int rA = (r0 > 48) ? 48 : r0;
    const int rB = (r1 > 48) ? 48 : r1;
    const float scl = 5.656854249492381f;
    float m0 = -3.0e38f, m1 = -3.0e38f;
    #pragma unroll
    for (int nf = 0; nf < 8; nf++) {
        int c0 = nf * 8 + tig * 2;
        float bAx = 0.f, bAy = 0.f, bBx = 0.f, bBy = 0.f;
        if (c0 <= 48) {
            float2 t0 = *(const float2*)&sB[rA * 52 + c0]; bAx = t0.x; bAy = t0.y;
            float2 t1 = *(const float2*)&sB[rB * 52 + c0]; bBx = t1.x; bBy = t1.y;
        }
        s[nf][0] = (c0     < 49) ? s[nf][0] * scl + bAx : -3.0e38f;
        s[nf][1] = (c0 + 1 < 49) ? s[nf][1] * scl + bAy : -3.0e38f;
        s[nf][2] = (c0     < 49) ? s[nf][2] * scl + bBx : -3.0e38f;
        s[nf][3] = (c0 + 1 < 49) ? s[nf][3] * scl + bBy : -3.0e38f;
        m0 = fmaxf(m0, fmaxf(s[nf][0], s[nf][1]));
        m1 = fmaxf(m1, fmaxf(s[nf][2], s[nf][3]));
    }
    m0 = fmaxf(m0, __shfl_xor_sync(0xffffffffu, m0, 1));
    m0 = fmaxf(m0, __shfl_xor_sync(0xffffffffu, m0, 2));
    m1 = fmaxf(m1, __shfl_xor_sync(0xffffffffu, m1, 1));
    m1 = fmaxf(m1, __shfl_xor_sync(0xffffffffu, m1, 2));

    float sum0 = 0.f, sum1 = 0.f;
    #pragma unroll
    for (int nf = 0; nf < 8; nf++) {
        s[nf][0] = __expf(s[nf][0] - m0);
        s[nf][1] = __expf(s[nf][1] - m0);
        s[nf][2] = __expf(s[nf][2] - m1);
        s[nf][3] = __expf(s[nf][3] - m1);
        sum0 += s[nf][0] + s[nf][1];
        sum1 += s[nf][2] + s[nf][3];
    }
    sum0 += __shfl_xor_sync(0xffffffffu, sum0, 1);
    sum0 += __shfl_xor_sync(0xffffffffu, sum0, 2);
    sum1 += __shfl_xor_sync(0xffffffffu, sum1, 1);
    sum1 += __shfl_xor_sync(0xffffffffu, sum1, 2);
    float inv0 = 1.f / sum0, inv1 = 1.f / sum1;

    // ---- pack P as bf16 hi/lo A-fragments ----
    uint32_t php[8][2], plp[8][2];
    #pragma unroll
    for (int nf = 0; nf < 8; nf++) {
        uint16_t h0, l0, h1, l1, h2, l2, h3, l3;
        split1(s[nf][0] * inv0, h0, l0);
        split1(s[nf][1] * inv0, h1, l1);
        split1(s[nf][2] * inv1, h2, l2);
        split1(s[nf][3] * inv1, h3, l3);
        php[nf][0] = (uint32_t)h0 | ((uint32_t)h1 << 16);
        plp[nf][0] = (uint32_t)l0 | ((uint32_t)l1 << 16);
        php[nf][1] = (uint32_t)h2 | ((uint32_t)h3 << 16);
        plp[nf][1] = (uint32_t)l2 | ((uint32_t)l3 << 16);
    }

    // ---- O = P @ V  (V row-major, B frags via ldmatrix.trans) ----
    float o[4][4];
    #pragma unroll
    for (int nf = 0; nf < 4; nf++)
        #pragma unroll
        for (int j = 0; j < 4; j++) o[nf][j] = 0.f;

    #pragma unroll
    for (int ks = 0; ks < 4; ks++) {
        uint32_t ah[4] = {php[2 * ks][0], php[2 * ks][1], php[2 * ks + 1][0], php[2 * ks + 1][1]};
        uint32_t al[4] = {plp[2 * ks][0], plp[2 * ks][1], plp[2 * ks + 1][0], plp[2 * ks + 1][1]};
        #pragma unroll
        for (int nfp = 0; nfp < 2; nfp++) {
            uint32_t bh[4], bl[4];
            uint32_t ba = boffV + (uint32_t)(ks * 16 * 40 + nfp * 16) * 2;
            ldsm_x4_trans(bh, vh_b + ba);
            ldsm_x4_trans(bl, vl_b + ba);
            mma16816(o[2 * nfp],     ah, bh[0], bh[1]);
            mma16816(o[2 * nfp],     ah, bl[0], bl[1]);
            mma16816(o[2 * nfp],     al, bh[0], bh[1]);
            mma16816(o[2 * nfp + 1], ah, bh[2], bh[3]);
            mma16816(o[2 * nfp + 1], ah, bl[2], bl[3]);
            mma16816(o[2 * nfp + 1], al, bh[2], bh[3]);
        }
    }

    // ---- store O hi/lo ----
    if (r0 <= 48) {
        int gr = rowbase + (r0 / 7) * 56 + r0 % 7;
        size_t base = (size_t)gr * 256 + head * 32;
        #pragma unroll
        for (int nf = 0; nf < 4; nf++) {
            int d = nf * 8 + tig * 2;
            uint16_t h0, l0, h1, l1;
            split1(o[nf][0], h0, l0);
            split1(o[nf][1], h1, l1);
            *(uint32_t*)(Ohi + base + d) = (uint32_t)h0 | ((uint32_t)h1 << 16);
            *(uint32_t*)(Olo + base + d) = (uint32_t)l0 | ((uint32_t)l1 << 16);
        }
    }
    if (r1 <= 48) {
        int gr = rowbase + (r1 / 7) * 56 + r1 % 7;
        size_t base = (size_t)gr * 256 + head * 32;
        #pragma unroll
        for (int nf = 0; nf < 4; nf++) {
            int d = nf * 8 + tig * 2;
            uint16_t h0, l0, h1, l1;
            split1(o[nf][2], h0, l0);
            split1(o[nf][3], h1, l1);
            *(uint32_t*)(Ohi + base + d) = (uint32_t)h0 | ((uint32_t)h1 << 16);
            *(uint32_t*)(Olo + base + d) = (uint32_t)l0 | ((uint32_t)l1 << 16);
        }
    }
}

// ---------------- host launcher ----------------
extern "C" void kernel_launch(void* const* d_in, const int* in_sizes, int n_in,
                              void* d_out, int out_size)
{
    const float* x    = (const float*)d_in[0];
    const float* pos  = (const float*)d_in[1];
    const float* wqkv = (const float*)d_in[2];
    const float* bqkv = (const float*)d_in[3];
    const float* wout = (const float*)d_in[4];
    const float* bout = (const float*)d_in[5];
    float* out = (float*)d_out;

    void *p_qkvh, *p_qkvl, *p_xh, *p_xl, *p_oh, *p_ol, *p_wqh, *p_wql, *p_woh, *p_wol, *p_bias;
    cudaGetSymbolAddress(&p_qkvh, g_qkvh);
    cudaGetSymbolAddress(&p_qkvl, g_qkvl);
    cudaGetSymbolAddress(&p_xh, g_x_hi);
    cudaGetSymbolAddress(&p_xl, g_x_lo);
    cudaGetSymbolAddress(&p_oh, g_o_hi);
    cudaGetSymbolAddress(&p_ol, g_o_lo);
    cudaGetSymbolAddress(&p_wqh, g_wq_hi);
    cudaGetSymbolAddress(&p_wql, g_wq_lo);
    cudaGetSymbolAddress(&p_woh, g_wo_hi);
    cudaGetSymbolAddress(&p_wol, g_wo_lo);
    cudaGetSymbolAddress(&p_bias, g_bias);

    cudaFuncSetAttribute(gemm_mma, cudaFuncAttributeMaxDynamicSharedMemorySize, SMO_TOTAL);

    prep_x<<<M_TOTAL * 256 / (256 * 8), 256>>>(x);
    prep_wqkv<<<256, 768>>>(wqkv);
    prep_wout<<<256, 256>>>(wout);
    prep_bias<<<20, 128>>>(pos);

    // GEMM1: qkv = x @ w_qkv + b_qkv -> bf16 hi/lo
    gemm_mma<<<(M_TOTAL / 128) * 3, 512, SMO_TOTAL>>>(
        (const __nv_bfloat16*)p_xh, (const __nv_bfloat16*)p_xl,
        (const __nv_bfloat16*)p_wqh, (const __nv_bfloat16*)p_wql,
        bqkv, nullptr, (__nv_bfloat16*)p_qkvh, (__nv_bfloat16*)p_qkvl, 768, 3);

    // tensor-core windowed attention: 4096 windows x 8 heads
    attn_kernel<<<32768, 128>>>(
        (const __nv_bfloat16*)p_qkvh, (const __nv_bfloat16*)p_qkvl,
        (const float*)p_bias,
        (__nv_bfloat16*)p_oh, (__nv_bfloat16*)p_ol);

    // GEMM2: out = O @ w_out + b_out -> fp32
    gemm_mma<<<(M_TOTAL / 128) * 1, 512, SMO_TOTAL>>>(
        (const __nv_bfloat16*)p_oh, (const __nv_bfloat16*)p_ol,
        (const __nv_bfloat16*)p_woh, (const __nv_bfloat16*)p_wol,
        bout, out, nullptr, nullptr, 256, 1);
}